// round 3
// baseline (speedup 1.0000x reference)
#include <cuda_runtime.h>
#include <math.h>
#include <float.h>

// Problem constants
#define NPAIR 1024          // B*R = 16*64
#define NOBJ  32
// conv1: 2->64, 5x5 VALID: 64 -> 60, pool -> 30
// conv2: 64->32, 5x5 VALID: 30 -> 26, pool -> 13, mean, fc 32->512

// ---------------- persistent prep scratch ----------------
__device__ float g_w2t[64 * 25 * 32];   // conv2 weights transposed: [c][p][q][o]
__device__ float g_P[128 * 36];         // conv1 SAT: [(o*2+box)][6][6]

// packed fp32x2 FMA (sm_103a): one issue slot = 2 fp32 FMAs
#define FMA2(acc, x, w) \
    asm("fma.rn.f32x2 %0, %1, %2, %0;" : "+l"(acc) : "l"(x), "l"(w))

// --------- exact integerization of mask intervals -----------
__device__ __forceinline__ int lo_int(float t) {   // smallest x with (x+0.5f >= t)
    int a = (int)ceilf(t - 0.5f);
    if ((float)a + 0.5f < t) a++;
    else if ((float)(a - 1) + 0.5f >= t) a--;
    return a;
}
__device__ __forceinline__ int hi_int(float t) {   // largest x with (x+0.5f <= t)
    int b = (int)floorf(t - 0.5f);
    if ((float)b + 0.5f > t) b--;
    else if ((float)(b + 1) + 0.5f <= t) b++;
    return b;
}

__device__ __forceinline__ float satv(const float* __restrict__ P,
                                      int Ay, int By, int Ax, int Bx, int i, int j) {
    int pl = min(max(Ay - i, 0), 5);
    int ph = min(max(By - i + 1, 0), 5);
    ph = max(ph, pl);
    int ql = min(max(Ax - j, 0), 5);
    int qh = min(max(Bx - j + 1, 0), 5);
    qh = max(qh, ql);
    return P[ph * 6 + qh] - P[pl * 6 + qh] - P[ph * 6 + ql] + P[pl * 6 + ql];
}

// ---------------- K0: prep (weight transpose + conv1 SAT build) ----------------
__global__ void prep_kernel(const float* __restrict__ conv2_w,
                            const float* __restrict__ conv1_w) {
    int idx = blockIdx.x * blockDim.x + threadIdx.x;
    if (idx < 64 * 25 * 32) {
        int o = idx & 31;
        int t2 = idx >> 5;
        int pq = t2 % 25;
        int c = t2 / 25;
        g_w2t[idx] = conv2_w[(o * 64 + c) * 25 + pq];
    } else if (idx < 64 * 25 * 32 + 128) {
        int u = idx - 64 * 25 * 32;
        const float* w = conv1_w + u * 25;
        float P[36];
        #pragma unroll
        for (int k = 0; k < 6; k++) { P[k] = 0.0f; P[k * 6] = 0.0f; }
        for (int a = 1; a < 6; a++)
            for (int b = 1; b < 6; b++)
                P[a * 6 + b] = P[(a - 1) * 6 + b] + P[a * 6 + b - 1]
                             - P[(a - 1) * 6 + b - 1] + w[(a - 1) * 5 + (b - 1)];
        for (int k = 0; k < 36; k++) g_P[u * 36 + k] = P[k];
    }
}

// ---------------- K1: fused rasterize+conv1+pool1 + conv2 + pool2 + mean + fc + relu ----
// block = one pair. blockDim = (32, 8). Thread (tx,ty): output row tx (<26), out-ch ty*4..+3.
// 4 channel-chunks of 16. Input stored DUPLICATED as float2 {v,v}: LDS.64 gives the packed
// f32x2 operand directly. Weights for adjacent out-channels adjacent -> LDS.64 packed.
#define CH_CHUNK 16
#define ROWP     31                         // row pitch in float2 (odd -> conflict-free)
#define IN_SM_F2 (CH_CHUNK * 30 * ROWP)     // 14880 float2 = 119040 B
#define W_SM_F   (CH_CHUNK * 25 * 32)       // 12800 floats = 51200 B
#define SMEM_BYTES (IN_SM_F2 * 8 + W_SM_F * 4 + 32 * 4)

typedef unsigned long long ull;
__device__ __forceinline__ float lo_f(ull v) { return __uint_as_float((unsigned)v); }
__device__ __forceinline__ float hi_f(ull v) { return __uint_as_float((unsigned)(v >> 32)); }

__global__ __launch_bounds__(256) void fused_kernel(
    const float* __restrict__ bboxes,
    const int* __restrict__ object_pairs,
    const float* __restrict__ conv1_b,
    const float* __restrict__ conv2_b,
    const float* __restrict__ fc_w,
    const float* __restrict__ fc_b,
    float* __restrict__ out) {
    extern __shared__ float sm[];
    float2* in_sm = (float2*)sm;                       // duplicated input chunk
    float*  w_sm  = sm + IN_SM_F2 * 2;                 // weight chunk
    float*  mean_sm = w_sm + W_SM_F;

    __shared__ float Psm[128 * 36];
    __shared__ float bsm[64];

    int tx = threadIdx.x, ty = threadIdx.y;
    int tid = ty * 32 + tx;
    int pair = blockIdx.x;

    for (int k = tid; k < 128 * 36; k += 256) Psm[k] = g_P[k];
    if (tid < 64) bsm[tid] = conv1_b[tid];

    // per-pair box params (computed redundantly; cheap)
    int bidx = pair >> 6;
    int i0 = object_pairs[pair * 2 + 0];
    int i1 = object_pairs[pair * 2 + 1];
    const float* p0 = bboxes + (bidx * NOBJ + i0) * 4;
    const float* p1 = bboxes + (bidx * NOBJ + i1) * 4;
    float b0x1 = p0[0], b0y1 = p0[1], b0x2 = p0[2], b0y2 = p0[3];
    float b1x1 = p1[0], b1y1 = p1[1], b1x2 = p1[2], b1y2 = p1[3];
    float ux1 = fminf(b0x1, b1x1), uy1 = fminf(b0y1, b1y1);
    float ux2 = fmaxf(b0x2, b1x2), uy2 = fmaxf(b0y2, b1y2);
    float uw = fmaxf(ux2 - ux1, 1e-6f), uh = fmaxf(uy2 - uy1, 1e-6f);

    int Ax0, Bx0, Ay0, By0, Ax1, Bx1, Ay1, By1;
    {
        float sx1 = (b0x1 - ux1) / uw * 64.0f, sy1 = (b0y1 - uy1) / uh * 64.0f;
        float sx2 = (b0x2 - ux1) / uw * 64.0f, sy2 = (b0y2 - uy1) / uh * 64.0f;
        Ax0 = lo_int(sx1); Bx0 = hi_int(sx2); Ay0 = lo_int(sy1); By0 = hi_int(sy2);
    }
    {
        float sx1 = (b1x1 - ux1) / uw * 64.0f, sy1 = (b1y1 - uy1) / uh * 64.0f;
        float sx2 = (b1x2 - ux1) / uw * 64.0f, sy2 = (b1y2 - uy1) / uh * 64.0f;
        Ax1 = lo_int(sx1); Bx1 = hi_int(sx2); Ay1 = lo_int(sy1); By1 = hi_int(sy2);
    }

    ull accA[26], accB[26];
    #pragma unroll
    for (int j = 0; j < 26; j++) { accA[j] = 0ull; accB[j] = 0ull; }

    #pragma unroll 1
    for (int cc = 0; cc < 4; cc++) {
        __syncthreads();    // protect prior chunk reads; also orders Psm/bsm on first iter

        // ---- build pool1 chunk (conv1 via SAT + 2x2 maxpool) directly in smem, duplicated
        for (int t = tid; t < CH_CHUNK * 900; t += 256) {
            int c  = t / 900;                 // local channel
            int cg = cc * CH_CHUNK + c;       // global conv1 out-channel
            int r  = t - c * 900;
            int pi = r / 30;
            int pj = r - pi * 30;
            const float* P0 = Psm + cg * 72;
            const float* P1 = P0 + 36;
            float m = -FLT_MAX;
            #pragma unroll
            for (int di = 0; di < 2; di++) {
                #pragma unroll
                for (int dj = 0; dj < 2; dj++) {
                    int i = 2 * pi + di, j = 2 * pj + dj;
                    float v = satv(P0, Ay0, By0, Ax0, Bx0, i, j)
                            + satv(P1, Ay1, By1, Ax1, Bx1, i, j);
                    m = fmaxf(m, v);
                }
            }
            float val = m + bsm[cg];
            in_sm[c * (30 * ROWP) + pi * ROWP + pj] = make_float2(val, val);
        }
        // ---- weight chunk
        for (int idx = tid; idx < W_SM_F; idx += 256)
            w_sm[idx] = g_w2t[cc * W_SM_F + idx];
        __syncthreads();

        // ---- conv2 partial sums, packed over output-channel pairs
        if (tx < 26) {
            #pragma unroll 1
            for (int c = 0; c < CH_CHUNK; c++) {
                #pragma unroll 1
                for (int p = 0; p < 5; p++) {
                    const ull* rp = (const ull*)(in_sm + c * (30 * ROWP) + (tx + p) * ROWP);
                    ull xd[30];
                    #pragma unroll
                    for (int j = 0; j < 30; j++) xd[j] = rp[j];
                    const float* wb = w_sm + (c * 25 + p * 5) * 32 + ty * 4;
                    #pragma unroll
                    for (int q = 0; q < 5; q++) {
                        ull wA = *(const ull*)(wb + q * 32);
                        ull wB = *(const ull*)(wb + q * 32 + 2);
                        #pragma unroll
                        for (int j = 0; j < 26; j++) {
                            FMA2(accA[j], xd[j + q], wA);
                            FMA2(accB[j], xd[j + q], wB);
                        }
                    }
                }
            }
        }
    }
    __syncthreads();

    // ---- conv2 outputs (+bias) to smem: conv_sm[o][row][col], reuse smem
    float* conv_sm = sm;
    if (tx < 26) {
        float b0 = __ldg(&conv2_b[ty * 4 + 0]);
        float b1 = __ldg(&conv2_b[ty * 4 + 1]);
        float b2 = __ldg(&conv2_b[ty * 4 + 2]);
        float b3 = __ldg(&conv2_b[ty * 4 + 3]);
        #pragma unroll
        for (int j = 0; j < 26; j++) {
            conv_sm[((ty * 4 + 0) * 26 + tx) * 26 + j] = lo_f(accA[j]) + b0;
            conv_sm[((ty * 4 + 1) * 26 + tx) * 26 + j] = hi_f(accA[j]) + b1;
            conv_sm[((ty * 4 + 2) * 26 + tx) * 26 + j] = lo_f(accB[j]) + b2;
            conv_sm[((ty * 4 + 3) * 26 + tx) * 26 + j] = hi_f(accB[j]) + b3;
        }
    }
    __syncthreads();

    // ---- pool2 (2x2 max) + spatial mean, warp per ty, deterministic shuffle reduce
    #pragma unroll
    for (int oo = 0; oo < 4; oo++) {
        int o = ty * 4 + oo;
        float s = 0.0f;
        for (int idx = tx; idx < 169; idx += 32) {
            int pi = idx / 13;
            int pj = idx - pi * 13;
            const float* b = conv_sm + (o * 26 + 2 * pi) * 26 + 2 * pj;
            float m = fmaxf(fmaxf(b[0], b[1]), fmaxf(b[26], b[27]));
            s += m;
        }
        #pragma unroll
        for (int off = 16; off; off >>= 1) s += __shfl_down_sync(0xffffffffu, s, off);
        if (tx == 0) mean_sm[o] = s * (1.0f / 169.0f);
    }
    __syncthreads();

    // ---- fc (32 -> 512) + relu
    for (int k = tid; k < 512; k += 256) {
        float v = __ldg(&fc_b[k]);
        const float4* fw = (const float4*)(fc_w + k * 32);
        #pragma unroll
        for (int c4 = 0; c4 < 8; c4++) {
            float4 w4 = __ldg(&fw[c4]);
            v = fmaf(mean_sm[c4 * 4 + 0], w4.x, v);
            v = fmaf(mean_sm[c4 * 4 + 1], w4.y, v);
            v = fmaf(mean_sm[c4 * 4 + 2], w4.z, v);
            v = fmaf(mean_sm[c4 * 4 + 3], w4.w, v);
        }
        out[pair * 512 + k] = fmaxf(v, 0.0f);
    }
}

// ---------------- launch ----------------
extern "C" void kernel_launch(void* const* d_in, const int* in_sizes, int n_in,
                              void* d_out, int out_size) {
    const float* bboxes       = (const float*)d_in[0];
    const int*   object_pairs = (const int*)d_in[3];
    const float* conv1_w      = (const float*)d_in[4];
    const float* conv1_b      = (const float*)d_in[5];
    const float* conv2_w      = (const float*)d_in[6];
    const float* conv2_b      = (const float*)d_in[7];
    const float* fc_w         = (const float*)d_in[8];
    const float* fc_b         = (const float*)d_in[9];
    float* out = (float*)d_out;

    static int attr_set = 0;
    if (!attr_set) {
        cudaFuncSetAttribute(fused_kernel, cudaFuncAttributeMaxDynamicSharedMemorySize, SMEM_BYTES);
        attr_set = 1;
    }

    prep_kernel<<<(64 * 25 * 32 + 128 + 255) / 256, 256>>>(conv2_w, conv1_w);
    fused_kernel<<<NPAIR, dim3(32, 8), SMEM_BYTES>>>(bboxes, object_pairs,
                                                     conv1_b, conv2_b, fc_w, fc_b, out);
}

// round 7
// speedup vs baseline: 7.0615x; 7.0615x over previous
#include <cuda_runtime.h>
#include <cuda_fp16.h>
#include <cstdint>
#include <math.h>
#include <float.h>

#define NPAIR 1024
#define NOBJ  32

// grid: pos = i*30 + j (i,j in 0..29 = pool1 30x30). Output i,j <= 25 (26x26).
// 49 m-tiles of 16 cover m 0..783. Tap offset = p*30+q (max 124); rows read <= 907.
#define XT_ROWS  912
#define XT_BYTES (XT_ROWS * 128)            // 116736: [row][64 ch f16], SW128 per 128B row
#define R2_BYTES 102400                     // overlay: Psm(18688) -> W fp16 -> Y f32(86528)
#define DSMEM    (XT_BYTES + R2_BYTES)      // 219136

// ---------------- persistent prep scratch ----------------
__device__ float g_P[128 * 36];                       // conv1 SAT per (outch,box)
__device__ __align__(16) __half g_wH[25 * 64 * 32];   // conv2 weights fp16 [tap][c][o]

// ---------------- warp-mma helpers ----------------
__device__ __forceinline__ uint32_t smem_u32(const void* p) {
    uint32_t a;
    asm("{ .reg .u64 t; cvta.to.shared.u64 t, %1; cvt.u32.u64 %0, t; }" : "=r"(a) : "l"(p));
    return a;
}
__device__ __forceinline__ void ldsm_x4(uint32_t* a, uint32_t addr) {
    asm volatile("ldmatrix.sync.aligned.m8n8.x4.shared.b16 {%0,%1,%2,%3}, [%4];"
                 : "=r"(a[0]), "=r"(a[1]), "=r"(a[2]), "=r"(a[3]) : "r"(addr));
}
__device__ __forceinline__ void ldsm_x2t(uint32_t* b, uint32_t addr) {
    asm volatile("ldmatrix.sync.aligned.m8n8.x2.trans.shared.b16 {%0,%1}, [%2];"
                 : "=r"(b[0]), "=r"(b[1]) : "r"(addr));
}
__device__ __forceinline__ void mma16816(float* d, const uint32_t* a, const uint32_t* b) {
    asm volatile("mma.sync.aligned.m16n8k16.row.col.f32.f16.f16.f32 "
                 "{%0,%1,%2,%3}, {%4,%5,%6,%7}, {%8,%9}, {%0,%1,%2,%3};"
                 : "+f"(d[0]), "+f"(d[1]), "+f"(d[2]), "+f"(d[3])
                 : "r"(a[0]), "r"(a[1]), "r"(a[2]), "r"(a[3]), "r"(b[0]), "r"(b[1]));
}

// --------- exact integerization of mask intervals (proven) -----------
__device__ __forceinline__ int lo_int(float t) {
    int a = (int)ceilf(t - 0.5f);
    if ((float)a + 0.5f < t) a++;
    else if ((float)(a - 1) + 0.5f >= t) a--;
    return a;
}
__device__ __forceinline__ int hi_int(float t) {
    int b = (int)floorf(t - 0.5f);
    if ((float)b + 0.5f > t) b--;
    else if ((float)(b + 1) + 0.5f <= t) b++;
    return b;
}

// ---------------- K0: prep ----------------
__global__ void prep_kernel(const float* __restrict__ conv2_w,
                            const float* __restrict__ conv1_w) {
    int idx = blockIdx.x * blockDim.x + threadIdx.x;
    if (idx < 25 * 64 * 32) {
        int o = idx & 31;
        int rest = idx >> 5;
        int c = rest & 63;
        int tap = rest >> 6;
        g_wH[idx] = __float2half(conv2_w[(o * 64 + c) * 25 + tap]);
    } else if (idx < 25 * 64 * 32 + 128) {
        int u = idx - 25 * 64 * 32;
        const float* w = conv1_w + u * 25;
        float P[36];
        #pragma unroll
        for (int k = 0; k < 6; k++) { P[k] = 0.0f; P[k * 6] = 0.0f; }
        for (int a = 1; a < 6; a++)
            for (int b = 1; b < 6; b++)
                P[a * 6 + b] = P[(a - 1) * 6 + b] + P[a * 6 + b - 1]
                             - P[(a - 1) * 6 + b - 1] + w[(a - 1) * 5 + (b - 1)];
        for (int k = 0; k < 36; k++) g_P[u * 36 + k] = P[k];
    }
}

// ---------------- K1: fused everything ----------------
__global__ __launch_bounds__(256, 1) void fused_kernel(
    const float* __restrict__ bboxes, const int* __restrict__ object_pairs,
    const float* __restrict__ conv1_b, const float* __restrict__ conv2_b,
    const float* __restrict__ fc_w, const float* __restrict__ fc_b,
    float* __restrict__ out) {
    extern __shared__ char sm[];
    float* Psm = (float*)(sm + XT_BYTES);           // overlay region
    float* bsm = Psm + 128 * 36;
    __shared__ float mean_sm[32];

    int tid = threadIdx.x, wid = tid >> 5, lane = tid & 31;
    int pair = blockIdx.x;
    uint32_t xt_addr = smem_u32(sm);
    uint32_t w_addr  = xt_addr + XT_BYTES;

    // ---- load SAT tables + conv1 bias into overlay region
    for (int k = tid; k < 128 * 36; k += 256) Psm[k] = g_P[k];
    if (tid < 64) bsm[tid] = conv1_b[tid];

    // ---- per-pair box geometry (exact)
    int bidx = pair >> 6;
    int i0 = object_pairs[pair * 2 + 0];
    int i1 = object_pairs[pair * 2 + 1];
    const float* p0 = bboxes + (bidx * NOBJ + i0) * 4;
    const float* p1 = bboxes + (bidx * NOBJ + i1) * 4;
    float b0x1 = p0[0], b0y1 = p0[1], b0x2 = p0[2], b0y2 = p0[3];
    float b1x1 = p1[0], b1y1 = p1[1], b1x2 = p1[2], b1y2 = p1[3];
    float ux1 = fminf(b0x1, b1x1), uy1 = fminf(b0y1, b1y1);
    float ux2 = fmaxf(b0x2, b1x2), uy2 = fmaxf(b0y2, b1y2);
    float uw = fmaxf(ux2 - ux1, 1e-6f), uh = fmaxf(uy2 - uy1, 1e-6f);
    int Ax0 = lo_int((b0x1 - ux1) / uw * 64.0f), Ay0 = lo_int((b0y1 - uy1) / uh * 64.0f);
    int Bx0 = hi_int((b0x2 - ux1) / uw * 64.0f), By0 = hi_int((b0y2 - uy1) / uh * 64.0f);
    int Ax1 = lo_int((b1x1 - ux1) / uw * 64.0f), Ay1 = lo_int((b1y1 - uy1) / uh * 64.0f);
    int Bx1 = hi_int((b1x2 - ux1) / uw * 64.0f), By1 = hi_int((b1y2 - uy1) / uh * 64.0f);
    __syncthreads();

    // ---- build Xt: rows = pos (i*30+j), 64 ch fp16, SW128-swizzled 128B rows
    for (int r = tid; r < XT_ROWS; r += 256) {
        uint32_t rx = (uint32_t)(r & 7) * 16u;
        char* rowp = sm + r * 128;
        if (r >= 900) {
            uint4 z = make_uint4(0, 0, 0, 0);
            #pragma unroll
            for (int g = 0; g < 8; g++) *(uint4*)(rowp + (((uint32_t)g * 16) ^ rx)) = z;
            continue;
        }
        int i = (int)((unsigned)r / 30u);
        int j = r - i * 30;
        int ia[8][4];
        #pragma unroll
        for (int s = 0; s < 4; s++) {
            int i2 = 2 * i + (s >> 1), j2 = 2 * j + (s & 1);
            int pl = min(max(Ay0 - i2, 0), 5), ph = max(min(max(By0 - i2 + 1, 0), 5), pl);
            int ql = min(max(Ax0 - j2, 0), 5), qh = max(min(max(Bx0 - j2 + 1, 0), 5), ql);
            ia[s * 2][0] = ph * 6 + qh; ia[s * 2][1] = pl * 6 + qh;
            ia[s * 2][2] = ph * 6 + ql; ia[s * 2][3] = pl * 6 + ql;
            pl = min(max(Ay1 - i2, 0), 5); ph = max(min(max(By1 - i2 + 1, 0), 5), pl);
            ql = min(max(Ax1 - j2, 0), 5); qh = max(min(max(Bx1 - j2 + 1, 0), 5), ql);
            ia[s * 2 + 1][0] = ph * 6 + qh; ia[s * 2 + 1][1] = pl * 6 + qh;
            ia[s * 2 + 1][2] = ph * 6 + ql; ia[s * 2 + 1][3] = pl * 6 + ql;
        }
        #pragma unroll 1
        for (int g = 0; g < 8; g++) {
            float v[8];
            #pragma unroll
            for (int cc = 0; cc < 8; cc++) {
                int c = g * 8 + cc;
                const float* P0 = Psm + c * 72;
                const float* P1 = P0 + 36;
                float m = -FLT_MAX;
                #pragma unroll
                for (int s = 0; s < 4; s++) {
                    const int* qa = ia[s * 2]; const int* qb = ia[s * 2 + 1];
                    float vv = P0[qa[0]] - P0[qa[1]] - P0[qa[2]] + P0[qa[3]]
                             + P1[qb[0]] - P1[qb[1]] - P1[qb[2]] + P1[qb[3]];
                    m = fmaxf(m, vv);
                }
                v[cc] = m + bsm[c];
            }
            __half2 h0 = __floats2half2_rn(v[0], v[1]);
            __half2 h1 = __floats2half2_rn(v[2], v[3]);
            __half2 h2 = __floats2half2_rn(v[4], v[5]);
            __half2 h3 = __floats2half2_rn(v[6], v[7]);
            uint4 u;
            u.x = *(uint32_t*)&h0; u.y = *(uint32_t*)&h1;
            u.z = *(uint32_t*)&h2; u.w = *(uint32_t*)&h3;
            *(uint4*)(rowp + (((uint32_t)g * 16) ^ rx)) = u;
        }
    }
    __syncthreads();

    // ---- overlay: copy fp16 weights over Psm region
    {
        const uint4* src = (const uint4*)g_wH;      // 6400 uint4
        uint4* dst = (uint4*)(sm + XT_BYTES);
        for (int k = tid; k < 6400; k += 256) dst[k] = src[k];
    }
    __syncthreads();

    // ---- mainloop: 25 taps x 4 k-tiles, D in registers
    float d[7][4][4];
    #pragma unroll
    for (int t = 0; t < 7; t++)
        #pragma unroll
        for (int nt = 0; nt < 4; nt++)
            #pragma unroll
            for (int e = 0; e < 4; e++) d[t][nt][e] = 0.0f;

    int l15 = lane & 15, lh = lane >> 4;
    #pragma unroll 1
    for (int tap = 0; tap < 25; tap++) {
        int off = (tap / 5) * 30 + (tap % 5);
        #pragma unroll
        for (int kt = 0; kt < 4; kt++) {
            uint32_t b[4][2];
            uint32_t baddr = w_addr + (uint32_t)tap * 4096 + (uint32_t)(kt * 16 + l15) * 64;
            #pragma unroll
            for (int nt = 0; nt < 4; nt++) ldsm_x2t(b[nt], baddr + nt * 16);
            #pragma unroll
            for (int t = 0; t < 7; t++) {
                int tile = wid + t * 8;
                if (tile < 49) {
                    int row = off + tile * 16 + l15;
                    uint32_t aaddr = xt_addr + (uint32_t)row * 128
                                   + (((uint32_t)(kt * 32 + lh * 16)) ^ ((uint32_t)(row & 7) * 16));
                    uint32_t a[4];
                    ldsm_x4(a, aaddr);
                    #pragma unroll
                    for (int nt = 0; nt < 4; nt++) mma16816(d[t][nt], a, b[nt]);
                }
            }
        }
    }
    __syncthreads();   // weights dead; Y overlays same region

    // ---- scatter D -> Y[o][i*26+j] (only valid 26x26 outputs)
    float* Yf = (float*)(sm + XT_BYTES);
    int g = lane >> 2, c0 = (lane & 3) * 2;
    #pragma unroll
    for (int t = 0; t < 7; t++) {
        int tile = wid + t * 8;
        if (tile < 49) {
            #pragma unroll
            for (int nt = 0; nt < 4; nt++) {
                int o = nt * 8 + c0;
                #pragma unroll
                for (int half = 0; half < 2; half++) {
                    int m = tile * 16 + g + half * 8;
                    int i = (int)((unsigned)m / 30u);
                    int j = m - i * 30;
                    if (i < 26 && j < 26) {
                        Yf[o * 676 + i * 26 + j]       = d[t][nt][half * 2 + 0];
                        Yf[(o + 1) * 676 + i * 26 + j] = d[t][nt][half * 2 + 1];
                    }
                }
            }
        }
    }
    __syncthreads();

    // ---- pool2 (2x2 max) + mean + conv2 bias ; warp per 4 out-channels
    #pragma unroll
    for (int oo = 0; oo < 4; oo++) {
        int o = wid * 4 + oo;
        float ssum = 0.0f;
        for (int idx = lane; idx < 169; idx += 32) {
            int pi = idx / 13, pj = idx - pi * 13;
            const float* b = Yf + (o * 26 + 2 * pi) * 26 + 2 * pj;
            ssum += fmaxf(fmaxf(b[0], b[1]), fmaxf(b[26], b[27]));
        }
        #pragma unroll
        for (int offs = 16; offs; offs >>= 1) ssum += __shfl_down_sync(0xffffffffu, ssum, offs);
        if (lane == 0) mean_sm[o] = ssum * (1.0f / 169.0f) + __ldg(&conv2_b[o]);
    }
    __syncthreads();

    // ---- fc (32 -> 512) + relu
    for (int k = tid; k < 512; k += 256) {
        float v = __ldg(&fc_b[k]);
        const float4* fw = (const float4*)(fc_w + k * 32);
        #pragma unroll
        for (int c4 = 0; c4 < 8; c4++) {
            float4 w4 = __ldg(&fw[c4]);
            v = fmaf(mean_sm[c4 * 4 + 0], w4.x, v);
            v = fmaf(mean_sm[c4 * 4 + 1], w4.y, v);
            v = fmaf(mean_sm[c4 * 4 + 2], w4.z, v);
            v = fmaf(mean_sm[c4 * 4 + 3], w4.w, v);
        }
        out[pair * 512 + k] = fmaxf(v, 0.0f);
    }
}

// ---------------- launch ----------------
extern "C" void kernel_launch(void* const* d_in, const int* in_sizes, int n_in,
                              void* d_out, int out_size) {
    const float* bboxes       = (const float*)d_in[0];
    const int*   object_pairs = (const int*)d_in[3];
    const float* conv1_w      = (const float*)d_in[4];
    const float* conv1_b      = (const float*)d_in[5];
    const float* conv2_w      = (const float*)d_in[6];
    const float* conv2_b      = (const float*)d_in[7];
    const float* fc_w         = (const float*)d_in[8];
    const float* fc_b         = (const float*)d_in[9];
    float* out = (float*)d_out;

    static int attr_set = 0;
    if (!attr_set) {
        cudaFuncSetAttribute(fused_kernel, cudaFuncAttributeMaxDynamicSharedMemorySize, DSMEM);
        attr_set = 1;
    }
    prep_kernel<<<(25 * 64 * 32 + 128 + 255) / 256, 256>>>(conv2_w, conv1_w);
    fused_kernel<<<NPAIR, 256, DSMEM>>>(bboxes, object_pairs, conv1_b, conv2_b, fc_w, fc_b, out);
}

// round 10
// speedup vs baseline: 7.6860x; 1.0884x over previous
#include <cuda_runtime.h>
#include <cuda_fp16.h>
#include <cstdint>
#include <math.h>
#include <float.h>

#define NPAIR 1024
#define NOBJ  32

// pos grid: m = i*30 + j (pool1 30x30). Valid outputs i,j <= 25. Valid m <= 775.
// rows read for valid m: m + p*30 + q <= 775 + 124 = 899  -> Xt needs rows 0..899 only.
#define XT_ROWS  900
#define XT_BYTES (XT_ROWS * 128)            // 115200: [row][64 ch f16], SW128 per 128B row
#define P_OFF    XT_BYTES
#define P_FLOATS (128 * 36)                 // SAT tables
#define B_OFF    (P_OFF + P_FLOATS * 4)     // conv1 bias
#define DSMEM    (B_OFF + 64 * 4)           // 133888 ; Y (86528B) overlays Xt after mainloop

// ---------------- persistent prep scratch ----------------
__device__ float g_P[128 * 36];                        // conv1 SAT per (outch,box)
__device__ __align__(16) uint4 g_wF4[25 * 4 * 2 * 32]; // B-fragments [tap][kt][nt2][lane]

// ---------------- warp-mma helpers ----------------
__device__ __forceinline__ uint32_t smem_u32(const void* p) {
    uint32_t a;
    asm("{ .reg .u64 t; cvta.to.shared.u64 t, %1; cvt.u32.u64 %0, t; }" : "=r"(a) : "l"(p));
    return a;
}
__device__ __forceinline__ void ldsm_x4(uint32_t* a, uint32_t addr) {
    asm volatile("ldmatrix.sync.aligned.m8n8.x4.shared.b16 {%0,%1,%2,%3}, [%4];"
                 : "=r"(a[0]), "=r"(a[1]), "=r"(a[2]), "=r"(a[3]) : "r"(addr));
}
__device__ __forceinline__ void mma16816(float* d, const uint32_t* a, uint32_t b0, uint32_t b1) {
    asm volatile("mma.sync.aligned.m16n8k16.row.col.f32.f16.f16.f32 "
                 "{%0,%1,%2,%3}, {%4,%5,%6,%7}, {%8,%9}, {%0,%1,%2,%3};"
                 : "+f"(d[0]), "+f"(d[1]), "+f"(d[2]), "+f"(d[3])
                 : "r"(a[0]), "r"(a[1]), "r"(a[2]), "r"(a[3]), "r"(b0), "r"(b1));
}

// --------- exact integerization of mask intervals (proven) -----------
__device__ __forceinline__ int lo_int(float t) {
    int a = (int)ceilf(t - 0.5f);
    if ((float)a + 0.5f < t) a++;
    else if ((float)(a - 1) + 0.5f >= t) a--;
    return a;
}
__device__ __forceinline__ int hi_int(float t) {
    int b = (int)floorf(t - 0.5f);
    if ((float)b + 0.5f > t) b--;
    else if ((float)(b + 1) + 0.5f <= t) b++;
    return b;
}

// ---------------- K0: prep ----------------
// g_wF4[tap][kt][nt2][lane]: exact mma.m16n8k16 B-fragments (what ldmatrix.x2.trans of
// W[tap] stored [c][o] produced in the passing R7 kernel):
//   b0(lane) = { w(c0, o), w(c0+1, o) },  b1 = { w(c0+8, o), w(c0+9, o) }
//   c0 = kt*16 + 2*(lane&3),  o = nt*8 + (lane>>2)
__global__ void prep_kernel(const float* __restrict__ conv2_w,
                            const float* __restrict__ conv1_w) {
    int idx = blockIdx.x * blockDim.x + threadIdx.x;
    if (idx < 6400) {
        int lane = idx & 31;
        int nt2  = (idx >> 5) & 1;
        int kt   = (idx >> 6) & 3;
        int tap  = idx >> 8;            // p*5+q
        int c0 = kt * 16 + 2 * (lane & 3);
        int orow = lane >> 2;
        auto wv = [&](int o, int c) -> __half {
            return __float2half(conv2_w[(o * 64 + c) * 25 + tap]);
        };
        auto pk = [&](__half lo, __half hi) -> uint32_t {
            __half2 h = __halves2half2(lo, hi);
            return *(uint32_t*)&h;
        };
        int oe = (nt2 * 2) * 8 + orow;
        int oo = (nt2 * 2 + 1) * 8 + orow;
        uint4 u;
        u.x = pk(wv(oe, c0),     wv(oe, c0 + 1));
        u.y = pk(wv(oe, c0 + 8), wv(oe, c0 + 9));
        u.z = pk(wv(oo, c0),     wv(oo, c0 + 1));
        u.w = pk(wv(oo, c0 + 8), wv(oo, c0 + 9));
        g_wF4[((tap * 4 + kt) * 2 + nt2) * 32 + lane] = u;
    } else if (idx < 6400 + 128) {
        int u = idx - 6400;
        const float* w = conv1_w + u * 25;
        float P[36];
        #pragma unroll
        for (int k = 0; k < 6; k++) { P[k] = 0.0f; P[k * 6] = 0.0f; }
        for (int a = 1; a < 6; a++)
            for (int b = 1; b < 6; b++)
                P[a * 6 + b] = P[(a - 1) * 6 + b] + P[a * 6 + b - 1]
                             - P[(a - 1) * 6 + b - 1] + w[(a - 1) * 5 + (b - 1)];
        for (int k = 0; k < 36; k++) g_P[u * 36 + k] = P[k];
    }
}

// ---------------- K1: fused everything (512 threads, 16 warps) ----------------
__global__ __launch_bounds__(512, 1) void fused_kernel(
    const float* __restrict__ bboxes, const int* __restrict__ object_pairs,
    const float* __restrict__ conv1_b, const float* __restrict__ conv2_b,
    const float* __restrict__ fc_w, const float* __restrict__ fc_b,
    float* __restrict__ out) {
    extern __shared__ char sm[];
    float* Psm = (float*)(sm + P_OFF);
    float* bsm = (float*)(sm + B_OFF);
    __shared__ float mean_sm[32];

    int tid = threadIdx.x, wid = tid >> 5, lane = tid & 31;
    int pair = blockIdx.x;
    uint32_t xt_addr = smem_u32(sm);

    for (int k = tid; k < P_FLOATS; k += 512) Psm[k] = g_P[k];
    if (tid < 64) bsm[tid] = conv1_b[tid];

    // ---- per-pair box geometry (exact)
    int bidx = pair >> 6;
    int i0 = object_pairs[pair * 2 + 0];
    int i1 = object_pairs[pair * 2 + 1];
    const float* p0 = bboxes + (bidx * NOBJ + i0) * 4;
    const float* p1 = bboxes + (bidx * NOBJ + i1) * 4;
    float b0x1 = p0[0], b0y1 = p0[1], b0x2 = p0[2], b0y2 = p0[3];
    float b1x1 = p1[0], b1y1 = p1[1], b1x2 = p1[2], b1y2 = p1[3];
    float ux1 = fminf(b0x1, b1x1), uy1 = fminf(b0y1, b1y1);
    float ux2 = fmaxf(b0x2, b1x2), uy2 = fmaxf(b0y2, b1y2);
    float uw = fmaxf(ux2 - ux1, 1e-6f), uh = fmaxf(uy2 - uy1, 1e-6f);
    int Ax0 = lo_int((b0x1 - ux1) / uw * 64.0f), Ay0 = lo_int((b0y1 - uy1) / uh * 64.0f);
    int Bx0 = hi_int((b0x2 - ux1) / uw * 64.0f), By0 = hi_int((b0y2 - uy1) / uh * 64.0f);
    int Ax1 = lo_int((b1x1 - ux1) / uw * 64.0f), Ay1 = lo_int((b1y1 - uy1) / uh * 64.0f);
    int Bx1 = hi_int((b1x2 - ux1) / uw * 64.0f), By1 = hi_int((b1y2 - uy1) / uh * 64.0f);
    __syncthreads();

    // ---- build Xt: rows 0..899 (m = i*30+j), 64 ch fp16, SW128-swizzled 128B rows
    for (int r = tid; r < XT_ROWS; r += 512) {
        uint32_t rx = (uint32_t)(r & 7) * 16u;
        char* rowp = sm + r * 128;
        int i = (int)((unsigned)r / 30u);
        int j = r - i * 30;
        int ia[8][4];
        #pragma unroll
        for (int s = 0; s < 4; s++) {
            int i2 = 2 * i + (s >> 1), j2 = 2 * j + (s & 1);
            int pl = min(max(Ay0 - i2, 0), 5), ph = max(min(max(By0 - i2 + 1, 0), 5), pl);
            int ql = min(max(Ax0 - j2, 0), 5), qh = max(min(max(Bx0 - j2 + 1, 0), 5), ql);
            ia[s * 2][0] = ph * 6 + qh; ia[s * 2][1] = pl * 6 + qh;
            ia[s * 2][2] = ph * 6 + ql; ia[s * 2][3] = pl * 6 + ql;
            pl = min(max(Ay1 - i2, 0), 5); ph = max(min(max(By1 - i2 + 1, 0), 5), pl);
            ql = min(max(Ax1 - j2, 0), 5); qh = max(min(max(Bx1 - j2 + 1, 0), 5), ql);
            ia[s * 2 + 1][0] = ph * 6 + qh; ia[s * 2 + 1][1] = pl * 6 + qh;
            ia[s * 2 + 1][2] = ph * 6 + ql; ia[s * 2 + 1][3] = pl * 6 + ql;
        }
        #pragma unroll 1
        for (int g = 0; g < 8; g++) {
            float v[8];
            #pragma unroll
            for (int cc = 0; cc < 8; cc++) {
                int c = g * 8 + cc;
                const float* P0 = Psm + c * 72;
                const float* P1 = P0 + 36;
                float m = -FLT_MAX;
                #pragma unroll
                for (int s = 0; s < 4; s++) {
                    const int* qa = ia[s * 2]; const int* qb = ia[s * 2 + 1];
                    float vv = P0[qa[0]] - P0[qa[1]] - P0[qa[2]] + P0[qa[3]]
                             + P1[qb[0]] - P1[qb[1]] - P1[qb[2]] + P1[qb[3]];
                    m = fmaxf(m, vv);
                }
                v[cc] = m + bsm[c];
            }
            __half2 h0 = __floats2half2_rn(v[0], v[1]);
            __half2 h1 = __floats2half2_rn(v[2], v[3]);
            __half2 h2 = __floats2half2_rn(v[4], v[5]);
            __half2 h3 = __floats2half2_rn(v[6], v[7]);
            uint4 u;
            u.x = *(uint32_t*)&h0; u.y = *(uint32_t*)&h1;
            u.z = *(uint32_t*)&h2; u.w = *(uint32_t*)&h3;
            *(uint4*)(rowp + (((uint32_t)g * 16) ^ rx)) = u;
        }
    }
    __syncthreads();

    // ---- mainloop: 25 taps x 4 kt; A from smem (ldsm), B from global fragments (LDG.128)
    float d[4][4][4];
    #pragma unroll
    for (int t = 0; t < 4; t++)
        #pragma unroll
        for (int nt = 0; nt < 4; nt++)
            #pragma unroll
            for (int e = 0; e < 4; e++) d[t][nt][e] = 0.0f;

    int l15 = lane & 15, lh = lane >> 4;
    #pragma unroll 1
    for (int tap = 0; tap < 25; tap++) {
        int off = (tap / 5) * 30 + (tap % 5);
        #pragma unroll
        for (int kt = 0; kt < 4; kt++) {
            const uint4* wf = g_wF4 + (tap * 4 + kt) * 64 + lane;
            uint4 B0 = __ldg(wf);
            uint4 B1 = __ldg(wf + 32);
            #pragma unroll
            for (int t = 0; t < 4; t++) {
                int tile = wid + t * 16;
                if (tile < 49) {
                    int row = off + tile * 16 + l15;
                    if (row > 899) row = 899;    // only feeds discarded outputs
                    uint32_t aaddr = xt_addr + (uint32_t)row * 128
                                   + (((uint32_t)(kt * 32 + lh * 16)) ^ ((uint32_t)(row & 7) * 16));
                    uint32_t a[4];
                    ldsm_x4(a, aaddr);
                    mma16816(d[t][0], a, B0.x, B0.y);
                    mma16816(d[t][1], a, B0.z, B0.w);
                    mma16816(d[t][2], a, B1.x, B1.y);
                    mma16816(d[t][3], a, B1.z, B1.w);
                }
            }
        }
    }
    __syncthreads();   // Xt dead; Y overlays it

    // ---- scatter D -> Y[o][i*26+j] (valid 26x26 only; each m owned by exactly one tile)
    float* Yf = (float*)sm;
    int g = lane >> 2, c0 = (lane & 3) * 2;
    #pragma unroll
    for (int t = 0; t < 4; t++) {
        int tile = wid + t * 16;
        if (tile < 49) {
            #pragma unroll
            for (int nt = 0; nt < 4; nt++) {
                int o = nt * 8 + c0;
                #pragma unroll
                for (int half = 0; half < 2; half++) {
                    int m = tile * 16 + g + half * 8;
                    int i = (int)((unsigned)m / 30u);
                    int j = m - i * 30;
                    if (i < 26 && j < 26) {
                        Yf[o * 676 + i * 26 + j]       = d[t][nt][half * 2 + 0];
                        Yf[(o + 1) * 676 + i * 26 + j] = d[t][nt][half * 2 + 1];
                    }
                }
            }
        }
    }
    __syncthreads();

    // ---- pool2 (2x2 max) + mean + conv2 bias ; warp per 2 out-channels
    #pragma unroll
    for (int oo = 0; oo < 2; oo++) {
        int o = wid * 2 + oo;
        float ssum = 0.0f;
        for (int idx = lane; idx < 169; idx += 32) {
            int pi = idx / 13, pj = idx - pi * 13;
            const float* b = Yf + (o * 26 + 2 * pi) * 26 + 2 * pj;
            ssum += fmaxf(fmaxf(b[0], b[1]), fmaxf(b[26], b[27]));
        }
        #pragma unroll
        for (int offs = 16; offs; offs >>= 1) ssum += __shfl_down_sync(0xffffffffu, ssum, offs);
        if (lane == 0) mean_sm[o] = ssum * (1.0f / 169.0f) + __ldg(&conv2_b[o]);
    }
    __syncthreads();

    // ---- fc (32 -> 512) + relu : one output per thread
    {
        int k = tid;
        float v = __ldg(&fc_b[k]);
        const float4* fw = (const float4*)(fc_w + k * 32);
        #pragma unroll
        for (int c4 = 0; c4 < 8; c4++) {
            float4 w4 = __ldg(&fw[c4]);
            v = fmaf(mean_sm[c4 * 4 + 0], w4.x, v);
            v = fmaf(mean_sm[c4 * 4 + 1], w4.y, v);
            v = fmaf(mean_sm[c4 * 4 + 2], w4.z, v);
            v = fmaf(mean_sm[c4 * 4 + 3], w4.w, v);
        }
        out[pair * 512 + k] = fmaxf(v, 0.0f);
    }
}

// ---------------- launch ----------------
extern "C" void kernel_launch(void* const* d_in, const int* in_sizes, int n_in,
                              void* d_out, int out_size) {
    const float* bboxes       = (const float*)d_in[0];
    const int*   object_pairs = (const int*)d_in[3];
    const float* conv1_w      = (const float*)d_in[4];
    const float* conv1_b      = (const float*)d_in[5];
    const float* conv2_w      = (const float*)d_in[6];
    const float* conv2_b      = (const float*)d_in[7];
    const float* fc_w         = (const float*)d_in[8];
    const float* fc_b         = (const float*)d_in[9];
    float* out = (float*)d_out;

    static int attr_set = 0;
    if (!attr_set) {
        cudaFuncSetAttribute(fused_kernel, cudaFuncAttributeMaxDynamicSharedMemorySize, DSMEM);
        attr_set = 1;
    }
    prep_kernel<<<(6400 + 128 + 255) / 256, 256>>>(conv2_w, conv1_w);
    fused_kernel<<<NPAIR, 512, DSMEM>>>(bboxes, object_pairs, conv1_b, conv2_b, fc_w, fc_b, out);
}

// round 11
// speedup vs baseline: 10.9533x; 1.4251x over previous
#include <cuda_runtime.h>
#include <cuda_fp16.h>
#include <cstdint>
#include <math.h>
#include <float.h>

#define NPAIR 1024
#define NOBJ  32

// pos grid: m = i*30 + j (pool1 30x30). Valid outputs i,j <= 25 -> m <= 775.
// rows read: m + p*30 + q <= 899 -> Xt rows 0..899.
#define XT_ROWS  900
#define XT_BYTES (XT_ROWS * 128)            // 115200: [row][64 ch f16], SW128 per 128B row
#define P_OFF    XT_BYTES                   // SAT tables, [box*64+c][pitch 73] floats
#define P_BYTES  (128 * 73 * 4)             // 37376
#define BIAS_OFF (P_OFF + P_BYTES)
#define V_OFF    (BIAS_OFF + 256)
#define V_HALFS  (441 * 64)                 // class LUT (<= 21*21 classes)
#define DSMEM    (V_OFF + V_HALFS * 2)      // 209280 ; Y (86528B) overlays Xt after mainloop

// ---------------- persistent prep scratch ----------------
__device__ float g_P[128 * 36];                        // conv1 SAT per (outch*2+box)
__device__ __align__(16) uint4 g_wF4[25 * 4 * 2 * 32]; // B-fragments [tap][kt][nt2][lane]

// ---------------- warp-mma helpers ----------------
__device__ __forceinline__ uint32_t smem_u32(const void* p) {
    uint32_t a;
    asm("{ .reg .u64 t; cvta.to.shared.u64 t, %1; cvt.u32.u64 %0, t; }" : "=r"(a) : "l"(p));
    return a;
}
__device__ __forceinline__ void ldsm_x4(uint32_t* a, uint32_t addr) {
    asm volatile("ldmatrix.sync.aligned.m8n8.x4.shared.b16 {%0,%1,%2,%3}, [%4];"
                 : "=r"(a[0]), "=r"(a[1]), "=r"(a[2]), "=r"(a[3]) : "r"(addr));
}
__device__ __forceinline__ void mma16816(float* d, const uint32_t* a, uint32_t b0, uint32_t b1) {
    asm volatile("mma.sync.aligned.m16n8k16.row.col.f32.f16.f16.f32 "
                 "{%0,%1,%2,%3}, {%4,%5,%6,%7}, {%8,%9}, {%0,%1,%2,%3};"
                 : "+f"(d[0]), "+f"(d[1]), "+f"(d[2]), "+f"(d[3])
                 : "r"(a[0]), "r"(a[1]), "r"(a[2]), "r"(a[3]), "r"(b0), "r"(b1));
}

// --------- exact integerization of mask intervals (proven) -----------
__device__ __forceinline__ int lo_int(float t) {
    int a = (int)ceilf(t - 0.5f);
    if ((float)a + 0.5f < t) a++;
    else if ((float)(a - 1) + 0.5f >= t) a--;
    return a;
}
__device__ __forceinline__ int hi_int(float t) {
    int b = (int)floorf(t - 0.5f);
    if ((float)b + 0.5f > t) b--;
    else if ((float)(b + 1) + 0.5f <= t) b++;
    return b;
}

// ---------------- K0: prep (unchanged from R10) ----------------
__global__ void prep_kernel(const float* __restrict__ conv2_w,
                            const float* __restrict__ conv1_w) {
    int idx = blockIdx.x * blockDim.x + threadIdx.x;
    if (idx < 6400) {
        int lane = idx & 31;
        int nt2  = (idx >> 5) & 1;
        int kt   = (idx >> 6) & 3;
        int tap  = idx >> 8;
        int c0 = kt * 16 + 2 * (lane & 3);
        int orow = lane >> 2;
        auto wv = [&](int o, int c) -> __half {
            return __float2half(conv2_w[(o * 64 + c) * 25 + tap]);
        };
        auto pk = [&](__half lo, __half hi) -> uint32_t {
            __half2 h = __halves2half2(lo, hi);
            return *(uint32_t*)&h;
        };
        int oe = (nt2 * 2) * 8 + orow;
        int oo = (nt2 * 2 + 1) * 8 + orow;
        uint4 u;
        u.x = pk(wv(oe, c0),     wv(oe, c0 + 1));
        u.y = pk(wv(oe, c0 + 8), wv(oe, c0 + 9));
        u.z = pk(wv(oo, c0),     wv(oo, c0 + 1));
        u.w = pk(wv(oo, c0 + 8), wv(oo, c0 + 9));
        g_wF4[((tap * 4 + kt) * 2 + nt2) * 32 + lane] = u;
    } else if (idx < 6400 + 128) {
        int u = idx - 6400;
        const float* w = conv1_w + u * 25;
        float P[36];
        #pragma unroll
        for (int k = 0; k < 6; k++) { P[k] = 0.0f; P[k * 6] = 0.0f; }
        for (int a = 1; a < 6; a++)
            for (int b = 1; b < 6; b++)
                P[a * 6 + b] = P[(a - 1) * 6 + b] + P[a * 6 + b - 1]
                             - P[(a - 1) * 6 + b - 1] + w[(a - 1) * 5 + (b - 1)];
        for (int k = 0; k < 36; k++) g_P[u * 36 + k] = P[k];
    }
}

// ---------------- K1: fused everything (512 threads) ----------------
__global__ __launch_bounds__(512, 1) void fused_kernel(
    const float* __restrict__ bboxes, const int* __restrict__ object_pairs,
    const float* __restrict__ conv1_b, const float* __restrict__ conv2_b,
    const float* __restrict__ fc_w, const float* __restrict__ fc_b,
    float* __restrict__ out) {
    extern __shared__ char sm[];
    float*  Psm = (float*)(sm + P_OFF);     // [box*64+c][73]
    float*  bsm = (float*)(sm + BIAS_OFF);
    __half* Vh  = (__half*)(sm + V_OFF);    // [cls][64]
    __shared__ float mean_sm[32];
    __shared__ int s_ycid[64], s_xcid[64];
    __shared__ uint32_t s_ycls[24], s_xcls[24];
    __shared__ int s_NY, s_NX;

    int tid = threadIdx.x, wid = tid >> 5, lane = tid & 31;
    int pair = blockIdx.x;
    uint32_t xt_addr = smem_u32(sm);

    // ---- load SAT tables (transposed to [box*64+c][73]) + conv1 bias
    for (int k = tid; k < 128 * 36; k += 512) {
        int u = k / 36, kk = k - u * 36;        // u = o*2 + box
        int o = u >> 1, box = u & 1;
        Psm[(box * 64 + o) * 73 + kk] = g_P[k];
    }
    if (tid < 64) bsm[tid] = conv1_b[tid];

    // ---- per-pair box geometry (exact)
    int bidx = pair >> 6;
    int i0 = object_pairs[pair * 2 + 0];
    int i1 = object_pairs[pair * 2 + 1];
    const float* p0 = bboxes + (bidx * NOBJ + i0) * 4;
    const float* p1 = bboxes + (bidx * NOBJ + i1) * 4;
    float b0x1 = p0[0], b0y1 = p0[1], b0x2 = p0[2], b0y2 = p0[3];
    float b1x1 = p1[0], b1y1 = p1[1], b1x2 = p1[2], b1y2 = p1[3];
    float ux1 = fminf(b0x1, b1x1), uy1 = fminf(b0y1, b1y1);
    float ux2 = fmaxf(b0x2, b1x2), uy2 = fmaxf(b0y2, b1y2);
    float uw = fmaxf(ux2 - ux1, 1e-6f), uh = fmaxf(uy2 - uy1, 1e-6f);
    int Ax0 = lo_int((b0x1 - ux1) / uw * 64.0f), Ay0 = lo_int((b0y1 - uy1) / uh * 64.0f);
    int Bx0 = hi_int((b0x2 - ux1) / uw * 64.0f), By0 = hi_int((b0y2 - uy1) / uh * 64.0f);
    int Ax1 = lo_int((b1x1 - ux1) / uw * 64.0f), Ay1 = lo_int((b1y1 - uy1) / uh * 64.0f);
    int Bx1 = hi_int((b1x2 - ux1) / uw * 64.0f), By1 = hi_int((b1y2 - uy1) / uh * 64.0f);

    // ---- class staircases (2 threads; <= 21 classes each, hard bound)
    if (tid == 0) {
        int n = 0; uint32_t prev = 0xFFFFFFFFu;
        for (int i2 = 0; i2 < 60; i2++) {
            int pl0 = min(max(Ay0 - i2, 0), 5), ph0 = max(min(max(By0 - i2 + 1, 0), 5), pl0);
            int pl1 = min(max(Ay1 - i2, 0), 5), ph1 = max(min(max(By1 - i2 + 1, 0), 5), pl1);
            uint32_t tup = (uint32_t)pl0 | ((uint32_t)ph0 << 4) | ((uint32_t)pl1 << 8) | ((uint32_t)ph1 << 12);
            if (tup != prev) { s_ycls[n++] = tup; prev = tup; }
            s_ycid[i2] = n - 1;
        }
        s_NY = n;
    } else if (tid == 32) {
        int n = 0; uint32_t prev = 0xFFFFFFFFu;
        for (int j2 = 0; j2 < 60; j2++) {
            int ql0 = min(max(Ax0 - j2, 0), 5), qh0 = max(min(max(Bx0 - j2 + 1, 0), 5), ql0);
            int ql1 = min(max(Ax1 - j2, 0), 5), qh1 = max(min(max(Bx1 - j2 + 1, 0), 5), ql1);
            uint32_t tup = (uint32_t)ql0 | ((uint32_t)qh0 << 4) | ((uint32_t)ql1 << 8) | ((uint32_t)qh1 << 12);
            if (tup != prev) { s_xcls[n++] = tup; prev = tup; }
            s_xcid[j2] = n - 1;
        }
        s_NX = n;
    }
    __syncthreads();

    // ---- build class LUT V[yc*NX+xc][c] (fp16, bias folded). Same 8-term order as before.
    int NX = s_NX, NYX = s_NY * NX;
    for (int cls = wid; cls < NYX; cls += 16) {
        int yc = (int)((unsigned)cls / (unsigned)NX);
        int xc = cls - yc * NX;
        uint32_t ty = s_ycls[yc], tx = s_xcls[xc];
        int pl0 = ty & 15, ph0 = (ty >> 4) & 15, pl1 = (ty >> 8) & 15, ph1 = (ty >> 12) & 15;
        int ql0 = tx & 15, qh0 = (tx >> 4) & 15, ql1 = (tx >> 8) & 15, qh1 = (tx >> 12) & 15;
        #pragma unroll
        for (int ch = 0; ch < 2; ch++) {
            int c = lane + ch * 32;
            const float* P0 = Psm + c * 73;           // box0
            const float* P1 = Psm + (64 + c) * 73;    // box1
            float vv = P0[ph0 * 6 + qh0] - P0[pl0 * 6 + qh0] - P0[ph0 * 6 + ql0] + P0[pl0 * 6 + ql0]
                     + P1[ph1 * 6 + qh1] - P1[pl1 * 6 + qh1] - P1[ph1 * 6 + ql1] + P1[pl1 * 6 + ql1]
                     + bsm[c];
            Vh[cls * 64 + c] = __float2half(vv);
        }
    }
    __syncthreads();

    // ---- build Xt rows: warp per row, 8 coalesced V loads + hmax + shuffle pack
    for (int r = wid; r < XT_ROWS; r += 16) {
        int i = (int)((unsigned)r / 30u);
        int j = r - i * 30;
        int ycA = s_ycid[2 * i], ycB = s_ycid[2 * i + 1];
        int xcA = s_xcid[2 * j], xcB = s_xcid[2 * j + 1];
        int b00 = (ycA * NX + xcA) * 64, b01 = (ycA * NX + xcB) * 64;
        int b10 = (ycB * NX + xcA) * 64, b11 = (ycB * NX + xcB) * 64;
        __half v1 = __hmax(__hmax(Vh[b00 + lane], Vh[b01 + lane]),
                           __hmax(Vh[b10 + lane], Vh[b11 + lane]));
        int l2 = lane + 32;
        __half v2 = __hmax(__hmax(Vh[b00 + l2], Vh[b01 + l2]),
                           __hmax(Vh[b10 + l2], Vh[b11 + l2]));
        uint32_t my = (uint32_t)__half_as_ushort(v1) | ((uint32_t)__half_as_ushort(v2) << 16);
        uint32_t ot = __shfl_xor_sync(0xffffffffu, my, 1);
        uint32_t val; int slot;
        if ((lane & 1) == 0) { slot = lane >> 1;        val = (my & 0xffffu) | (ot << 16); }
        else                 { slot = 16 + (lane >> 1); val = (ot >> 16) | (my & 0xffff0000u); }
        *(uint32_t*)(sm + r * 128 + (((uint32_t)slot * 4) ^ ((uint32_t)(r & 7) * 16))) = val;
    }
    __syncthreads();

    // ---- mainloop: 25 taps x 4 kt; A via ldsm from smem, B fragments via LDG (unchanged)
    float d[4][4][4];
    #pragma unroll
    for (int t = 0; t < 4; t++)
        #pragma unroll
        for (int nt = 0; nt < 4; nt++)
            #pragma unroll
            for (int e = 0; e < 4; e++) d[t][nt][e] = 0.0f;

    int l15 = lane & 15, lh = lane >> 4;
    #pragma unroll 1
    for (int tap = 0; tap < 25; tap++) {
        int off = (tap / 5) * 30 + (tap % 5);
        #pragma unroll
        for (int kt = 0; kt < 4; kt++) {
            const uint4* wf = g_wF4 + (tap * 4 + kt) * 64 + lane;
            uint4 B0 = __ldg(wf);
            uint4 B1 = __ldg(wf + 32);
            #pragma unroll
            for (int t = 0; t < 4; t++) {
                int tile = wid + t * 16;
                if (tile < 49) {
                    int row = off + tile * 16 + l15;
                    if (row > 899) row = 899;    // only feeds discarded outputs
                    uint32_t aaddr = xt_addr + (uint32_t)row * 128
                                   + (((uint32_t)(kt * 32 + lh * 16)) ^ ((uint32_t)(row & 7) * 16));
                    uint32_t a[4];
                    ldsm_x4(a, aaddr);
                    mma16816(d[t][0], a, B0.x, B0.y);
                    mma16816(d[t][1], a, B0.z, B0.w);
                    mma16816(d[t][2], a, B1.x, B1.y);
                    mma16816(d[t][3], a, B1.z, B1.w);
                }
            }
        }
    }
    __syncthreads();   // Xt dead; Y overlays it

    // ---- scatter D -> Y[o][i*26+j]
    float* Yf = (float*)sm;
    int g = lane >> 2, c0 = (lane & 3) * 2;
    #pragma unroll
    for (int t = 0; t < 4; t++) {
        int tile = wid + t * 16;
        if (tile < 49) {
            #pragma unroll
            for (int nt = 0; nt < 4; nt++) {
                int o = nt * 8 + c0;
                #pragma unroll
                for (int half = 0; half < 2; half++) {
                    int m = tile * 16 + g + half * 8;
                    int i = (int)((unsigned)m / 30u);
                    int j = m - i * 30;
                    if (i < 26 && j < 26) {
                        Yf[o * 676 + i * 26 + j]       = d[t][nt][half * 2 + 0];
                        Yf[(o + 1) * 676 + i * 26 + j] = d[t][nt][half * 2 + 1];
                    }
                }
            }
        }
    }
    __syncthreads();

    // ---- pool2 (2x2 max) + mean + conv2 bias ; warp per 2 out-channels
    #pragma unroll
    for (int oo = 0; oo < 2; oo++) {
        int o = wid * 2 + oo;
        float ssum = 0.0f;
        for (int idx = lane; idx < 169; idx += 32) {
            int pi = idx / 13, pj = idx - pi * 13;
            const float* b = Yf + (o * 26 + 2 * pi) * 26 + 2 * pj;
            ssum += fmaxf(fmaxf(b[0], b[1]), fmaxf(b[26], b[27]));
        }
        #pragma unroll
        for (int offs = 16; offs; offs >>= 1) ssum += __shfl_down_sync(0xffffffffu, ssum, offs);
        if (lane == 0) mean_sm[o] = ssum * (1.0f / 169.0f) + __ldg(&conv2_b[o]);
    }
    __syncthreads();

    // ---- fc (32 -> 512) + relu : one output per thread
    {
        int k = tid;
        float v = __ldg(&fc_b[k]);
        const float4* fw = (const float4*)(fc_w + k * 32);
        #pragma unroll
        for (int c4 = 0; c4 < 8; c4++) {
            float4 w4 = __ldg(&fw[c4]);
            v = fmaf(mean_sm[c4 * 4 + 0], w4.x, v);
            v = fmaf(mean_sm[c4 * 4 + 1], w4.y, v);
            v = fmaf(mean_sm[c4 * 4 + 2], w4.z, v);
            v = fmaf(mean_sm[c4 * 4 + 3], w4.w, v);
        }
        out[pair * 512 + k] = fmaxf(v, 0.0f);
    }
}

// ---------------- launch ----------------
extern "C" void kernel_launch(void* const* d_in, const int* in_sizes, int n_in,
                              void* d_out, int out_size) {
    const float* bboxes       = (const float*)d_in[0];
    const int*   object_pairs = (const int*)d_in[3];
    const float* conv1_w      = (const float*)d_in[4];
    const float* conv1_b      = (const float*)d_in[5];
    const float* conv2_w      = (const float*)d_in[6];
    const float* conv2_b      = (const float*)d_in[7];
    const float* fc_w         = (const float*)d_in[8];
    const float* fc_b         = (const float*)d_in[9];
    float* out = (float*)d_out;

    static int attr_set = 0;
    if (!attr_set) {
        cudaFuncSetAttribute(fused_kernel, cudaFuncAttributeMaxDynamicSharedMemorySize, DSMEM);
        attr_set = 1;
    }
    prep_kernel<<<(6400 + 128 + 255) / 256, 256>>>(conv2_w, conv1_w);
    fused_kernel<<<NPAIR, 512, DSMEM>>>(bboxes, object_pairs, conv1_b, conv2_b, fc_w, fc_b, out);
}